// round 1
// baseline (speedup 1.0000x reference)
#include <cuda_runtime.h>

#define NN 35
#define NE 1190

// ---------------- scratch (device globals; no allocation allowed) ----------------
__device__ float g_h1[NN * 256];
__device__ float g_h2[NN * 256];
__device__ float g_h3[NN * 64];
__device__ float g_msg[NE * 256];
__device__ float g_w2q[256 * 7 * 256];   // [i][v(6w+bias)][o]
__device__ float g_w3q[256 * 7 * 64];
__device__ float g_l2t[256 * 256];       // lin2_w transposed [i][o]
__device__ float g_l3t[256 * 64];        // lin3_w transposed [i][o]
__device__ float g_ea8[NE * 8];          // edge_attr padded to 8 floats
__device__ int   g_perm[NE];
__device__ int   g_off[NN + 1];
__device__ float g_inv[NN];

// ---------------- prep: deterministic CSR by dst + pad edge_attr ----------------
__global__ void k_prep(const float* __restrict__ ea, const int* __restrict__ eidx) {
    __shared__ int s_dst[NE];
    __shared__ int s_coff[8 * NN];
    __shared__ int s_off[NN + 1];
    int tid = threadIdx.x;
    for (int e = tid; e < NE; e += blockDim.x) s_dst[e] = eidx[NE + e];
    __syncthreads();
    if (tid < 8 * NN) {
        int c = tid / NN, n = tid % NN;
        int lo = c * 149, hi = min(lo + 149, NE);
        int cnt = 0;
        for (int e = lo; e < hi; e++) cnt += (s_dst[e] == n);
        s_coff[c * NN + n] = cnt;
    }
    __syncthreads();
    if (tid == 0) {
        int off = 0;
        for (int n = 0; n < NN; n++) {
            s_off[n] = off;
            for (int c = 0; c < 8; c++) {
                int t = s_coff[c * NN + n];
                s_coff[c * NN + n] = off;
                off += t;
            }
        }
        s_off[NN] = off;
    }
    __syncthreads();
    if (tid < 8 * NN) {
        int c = tid / NN, n = tid % NN;
        int lo = c * 149, hi = min(lo + 149, NE);
        int p = s_coff[c * NN + n];
        for (int e = lo; e < hi; e++)
            if (s_dst[e] == n) g_perm[p++] = e;
    }
    if (tid <= NN) g_off[tid] = s_off[tid];
    if (tid < NN) {
        int cnt = s_off[tid + 1] - s_off[tid];
        g_inv[tid] = 1.0f / (float)max(cnt, 1);
    }
    for (int idx = tid; idx < NE * 8; idx += blockDim.x) {
        int e = idx >> 3, v = idx & 7;
        g_ea8[idx] = (v < 6) ? ea[e * 6 + v] : 0.f;
    }
}

// ---------------- weight packing ----------------
__global__ void k_pack2(const float* __restrict__ w, const float* __restrict__ b) {
    int i = blockIdx.x, o = threadIdx.x;          // 256 x 256
    int io = i * 256 + o;
#pragma unroll
    for (int v = 0; v < 6; v++) g_w2q[(i * 7 + v) * 256 + o] = w[io * 6 + v];
    g_w2q[(i * 7 + 6) * 256 + o] = b[io];
}
__global__ void k_pack3(const float* __restrict__ w, const float* __restrict__ b) {
    int i = blockIdx.x, o = threadIdx.x;          // 256 x 64
    int io = i * 64 + o;
#pragma unroll
    for (int v = 0; v < 6; v++) g_w3q[(i * 7 + v) * 64 + o] = w[io * 6 + v];
    g_w3q[(i * 7 + 6) * 64 + o] = b[io];
}
__global__ void k_packlin(const float* __restrict__ l2, const float* __restrict__ l3) {
    int b = blockIdx.x, i = threadIdx.x;          // 320 x 256
    if (b < 256) g_l2t[i * 256 + b] = l2[b * 256 + i];
    else {
        int o = b - 256;                           // 64 rows
        g_l3t[i * 64 + o] = l3[o * 256 + i];
    }
}

// ---------------- layer 1 messages (c_in = 1) ----------------
__global__ void k_l1(const float* __restrict__ x, const float* __restrict__ ea,
                     const int* __restrict__ eidx,
                     const float* __restrict__ w1, const float* __restrict__ b1) {
    int e = blockIdx.x, o = threadIdx.x;
    float xs = x[eidx[e]];
    const float* a = ea + e * 6;
    float t = b1[o];
#pragma unroll
    for (int v = 0; v < 6; v++) t = fmaf(w1[o * 6 + v], a[v], t);
    t = fmaxf(t, 0.f);
    g_msg[e * 256 + o] = xs * t;
}

// ---------------- layer 1 aggregate + node update ----------------
__global__ void k_agg1(const float* __restrict__ x, const float* __restrict__ lw,
                       const float* __restrict__ b) {
    int n = blockIdx.x, o = threadIdx.x;
    int j0 = g_off[n], j1 = g_off[n + 1];
    float acc = 0.f;
    for (int j = j0; j < j1; j++) acc += g_msg[g_perm[j] * 256 + o];
    float h = fmaxf(fmaf(acc, g_inv[n], fmaf(x[n], lw[o], b[o])), 0.f);
    g_h1[n * 256 + o] = h;
}

// ---------------- heavy message kernel (layers 2/3) ----------------
// o in lanes (64 per block-chunk), ET edges in registers, i split across NS groups.
template <int ET, int NS, int L>
__global__ void __launch_bounds__(64 * NS) k_msg(const int* __restrict__ eidx) {
    constexpr int OTOT = (L == 3) ? 64 : 256;
    constexpr int NT = 64 * NS;
    constexpr int IPS = 256 / NS;
    const float* __restrict__ wq  = (L == 3) ? g_w3q : g_w2q;
    const float* __restrict__ hin = (L == 3) ? g_h2 : g_h1;

    __shared__ float xs_sm[ET * 256];
    __shared__ float ea_sm[ET * 8];
    __shared__ float sred[64 * (ET + 1)];

    int tid = threadIdx.x;
    int e0 = blockIdx.x * ET;
    int oc = blockIdx.y * 64;
    int ol = tid & 63;
    int o = oc + ol;
    int isub = tid >> 6;

    for (int idx = tid; idx < ET * 8; idx += NT) {
        int e = e0 + (idx >> 3);
        if (e >= NE) e = 0;
        ea_sm[idx] = g_ea8[e * 8 + (idx & 7)];
    }
    for (int idx = tid; idx < ET * 256; idx += NT) {
        int e = e0 + (idx >> 8);
        if (e >= NE) e = 0;
        xs_sm[idx] = hin[eidx[e] * 256 + (idx & 255)];
    }
    __syncthreads();

    float acc[ET];
#pragma unroll
    for (int e = 0; e < ET; e++) acc[e] = 0.f;

    const int i0base = isub * IPS;
    for (int itb = 0; itb < IPS / 4; itb++) {
        const int i0 = i0base + itb * 4;
        float w[4][7];
#pragma unroll
        for (int ii = 0; ii < 4; ii++) {
            const float* wp = wq + (size_t)(i0 + ii) * 7 * OTOT + o;
#pragma unroll
            for (int v = 0; v < 7; v++) w[ii][v] = wp[v * OTOT];
        }
#pragma unroll
        for (int e = 0; e < ET; e++) {
            float4 a4 = *(const float4*)(ea_sm + e * 8);
            float2 a2 = *(const float2*)(ea_sm + e * 8 + 4);
            float4 x4 = *(const float4*)(xs_sm + e * 256 + i0);
            float xv[4] = {x4.x, x4.y, x4.z, x4.w};
            float s = acc[e];
#pragma unroll
            for (int ii = 0; ii < 4; ii++) {
                float t = fmaf(w[ii][0], a4.x, w[ii][6]);
                t = fmaf(w[ii][1], a4.y, t);
                t = fmaf(w[ii][2], a4.z, t);
                t = fmaf(w[ii][3], a4.w, t);
                t = fmaf(w[ii][4], a2.x, t);
                t = fmaf(w[ii][5], a2.y, t);
                s = fmaf(xv[ii], fmaxf(t, 0.f), s);
            }
            acc[e] = s;
        }
    }

    // reduce across i-sub groups (deterministic phased adds)
    for (int p = 0; p < NS; p++) {
        if (isub == p) {
            if (p == 0) {
#pragma unroll
                for (int e = 0; e < ET; e++) sred[ol * (ET + 1) + e] = acc[e];
            } else {
#pragma unroll
                for (int e = 0; e < ET; e++) sred[ol * (ET + 1) + e] += acc[e];
            }
        }
        __syncthreads();
    }
    for (int idx = tid; idx < ET * 64; idx += NT) {
        int e = idx >> 6, oo = idx & 63;
        int ee = e0 + e;
        if (ee < NE) g_msg[ee * OTOT + oc + oo] = sred[oo * (ET + 1) + e];
    }
}

// ---------------- layers 2/3 aggregate + root linear + relu ----------------
template <int L>
__global__ void k_agg23(const float* __restrict__ b) {
    constexpr int OTOT = (L == 3) ? 64 : 256;
    const float* __restrict__ hin = (L == 3) ? g_h2 : g_h1;
    const float* __restrict__ lt  = (L == 3) ? g_l3t : g_l2t;
    float* __restrict__ hout      = (L == 3) ? g_h3 : g_h2;

    __shared__ float hn[256];
    int n = blockIdx.x, o = threadIdx.x;
    for (int i = o; i < 256; i += OTOT) hn[i] = hin[n * 256 + i];
    __syncthreads();

    int j0 = g_off[n], j1 = g_off[n + 1];
    float acc = 0.f;
    for (int j = j0; j < j1; j++) acc += g_msg[g_perm[j] * OTOT + o];

    float l0 = b[o], l1 = 0.f, l2v = 0.f, l3v = 0.f;
#pragma unroll 4
    for (int i = 0; i < 256; i += 4) {
        l0  = fmaf(hn[i],     lt[(i)     * OTOT + o], l0);
        l1  = fmaf(hn[i + 1], lt[(i + 1) * OTOT + o], l1);
        l2v = fmaf(hn[i + 2], lt[(i + 2) * OTOT + o], l2v);
        l3v = fmaf(hn[i + 3], lt[(i + 3) * OTOT + o], l3v);
    }
    float lin = (l0 + l1) + (l2v + l3v);
    hout[n * OTOT + o] = fmaxf(fmaf(acc, g_inv[n], lin), 0.f);
}

// ---------------- CBT: pairwise L1 distances ----------------
__global__ void k_cbt(float* __restrict__ out) {
    int p = blockIdx.x;
    int a = p / NN, bb = p % NN;
    int c = threadIdx.x;  // 32
    float d = fabsf(g_h3[a * 64 + c] - g_h3[bb * 64 + c]) +
              fabsf(g_h3[a * 64 + c + 32] - g_h3[bb * 64 + c + 32]);
#pragma unroll
    for (int s = 16; s; s >>= 1) d += __shfl_xor_sync(0xffffffffu, d, s);
    if (c == 0) out[p] = d;
}

// ---------------- launch ----------------
extern "C" void kernel_launch(void* const* d_in, const int* in_sizes, int n_in,
                              void* d_out, int out_size) {
    const float* x   = (const float*)d_in[0];
    const float* ea  = (const float*)d_in[1];
    const int*   ei  = (const int*)d_in[2];
    const float* n1w = (const float*)d_in[3];
    const float* n1b = (const float*)d_in[4];
    const float* l1w = (const float*)d_in[5];
    const float* b1  = (const float*)d_in[6];
    const float* n2w = (const float*)d_in[7];
    const float* n2b = (const float*)d_in[8];
    const float* l2w = (const float*)d_in[9];
    const float* b2  = (const float*)d_in[10];
    const float* n3w = (const float*)d_in[11];
    const float* n3b = (const float*)d_in[12];
    const float* l3w = (const float*)d_in[13];
    const float* b3  = (const float*)d_in[14];
    float* out = (float*)d_out;
    (void)in_sizes; (void)n_in; (void)out_size;

    k_prep<<<1, 512>>>(ea, ei);
    k_pack2<<<256, 256>>>(n2w, n2b);
    k_pack3<<<256, 64>>>(n3w, n3b);
    k_packlin<<<320, 256>>>(l2w, l3w);

    k_l1<<<NE, 256>>>(x, ea, ei, n1w, n1b);
    k_agg1<<<NN, 256>>>(x, l1w, b1);

    k_msg<32, 4, 2><<<dim3((NE + 31) / 32, 4), 256>>>(ei);   // layer 2: 38x4 blocks
    k_agg23<2><<<NN, 256>>>(b2);

    k_msg<8, 4, 3><<<dim3((NE + 7) / 8, 1), 256>>>(ei);      // layer 3: 149 blocks
    k_agg23<3><<<NN, 64>>>(b3);

    k_cbt<<<NN * NN, 32>>>(out);
}